// round 7
// baseline (speedup 1.0000x reference)
#include <cuda_runtime.h>
#include <cstdint>

// CRF broadcast-add: out[b,l,i,j] = emission[b,l,j] + transition[i,j]
// B=32, L=512, T=64 -> 16384 tiles of 64x64 fp32 (16 KB each).
//
// R7: stores go through the TMA bulk-async engine instead of per-warp STG.128.
// R3/R6 evidence: no pipe saturated, ~6 cyc per warp-STG.128 per SM -> the
// LSU store-issue path was the binder. Each CTA computes a tile into SMEM
// (double-buffered) and issues one 16KB cp.async.bulk store per tile.

constexpr int Tc = 64;
constexpr int BL = 32 * 512;                // 16384 tiles
constexpr int TILE_F4 = (Tc * Tc) / 4;      // 1024 float4 = 16 KB
constexpr int EM_F4_PER_TILE = Tc / 4;      // 16
constexpr int THREADS = 256;
constexpr int F4_PER_THREAD = TILE_F4 / THREADS;  // 4
constexpr unsigned TILE_BYTES = TILE_F4 * 16;     // 16384

__device__ __forceinline__ uint32_t smem_u32(const void* p) {
    uint32_t a;
    asm("{ .reg .u64 tmp; cvta.to.shared.u64 tmp, %1; cvt.u32.u64 %0, tmp; }"
        : "=r"(a) : "l"(p));
    return a;
}

__global__ void __launch_bounds__(THREADS, 4)
crf_broadcast_add_tma(const float4* __restrict__ em4,
                      const float4* __restrict__ tr4,
                      float4* __restrict__ out4)
{
    __shared__ float4 sbuf[2][TILE_F4];     // 2 x 16 KB double buffer

    const int t  = threadIdx.x;
    const int j4 = t & (EM_F4_PER_TILE - 1);

    // Tile-invariant transition rows -> registers.
    float4 tr[F4_PER_THREAD];
#pragma unroll
    for (int k = 0; k < F4_PER_THREAD; ++k)
        tr[k] = __ldg(&tr4[t + THREADS * k]);

    // Contiguous chunk of tiles per CTA.
    const int per   = (BL + gridDim.x - 1) / gridDim.x;
    const int start = blockIdx.x * per;
    const int end   = (start + per < BL) ? (start + per) : BL;

    int it = 0;
    for (int bl = start; bl < end; ++bl, ++it) {
        const int buf = it & 1;

        // Reclaim the buffer used two tiles ago: wait until its smem reads
        // by the bulk engine are done (<=1 group outstanding).
        if (t == 0 && it >= 2)
            asm volatile("cp.async.bulk.wait_group.read 1;" ::: "memory");
        __syncthreads();

        const float4 e = __ldg(&em4[(size_t)bl * EM_F4_PER_TILE + j4]);
#pragma unroll
        for (int k = 0; k < F4_PER_THREAD; ++k) {
            float4 v;
            v.x = e.x + tr[k].x;
            v.y = e.y + tr[k].y;
            v.z = e.z + tr[k].z;
            v.w = e.w + tr[k].w;
            sbuf[buf][t + THREADS * k] = v;
        }
        __syncthreads();

        if (t == 0) {
            asm volatile("fence.proxy.async.shared::cta;" ::: "memory");
            const uint32_t saddr = smem_u32(&sbuf[buf][0]);
            float4* gptr = out4 + (size_t)bl * TILE_F4;
            asm volatile(
                "cp.async.bulk.global.shared::cta.bulk_group [%0], [%1], %2;"
                :: "l"(gptr), "r"(saddr), "r"(TILE_BYTES) : "memory");
            asm volatile("cp.async.bulk.commit_group;" ::: "memory");
        }
    }

    // Drain all outstanding bulk stores before CTA exit.
    if (t == 0)
        asm volatile("cp.async.bulk.wait_group 0;" ::: "memory");
    __syncthreads();
}

extern "C" void kernel_launch(void* const* d_in, const int* in_sizes, int n_in,
                              void* d_out, int out_size)
{
    const float4* em4 = (const float4*)d_in[0];   // emission [B, L, T] fp32
    const float4* tr4 = (const float4*)d_in[1];   // transition [T, T] fp32
    float4* out4      = (float4*)d_out;           // [B, L, T, T] fp32

    const int grid = 152 * 4;   // 4 CTAs/SM (32 KB smem each), 152 SMs
    crf_broadcast_add_tma<<<grid, THREADS>>>(em4, tr4, out4);
}